// round 1
// baseline (speedup 1.0000x reference)
#include <cuda_runtime.h>
#include <math.h>

#define BB 1024
#define DD 64
#define HH 128
#define TJ 32

// Scratch (allocation-free rule: __device__ globals)
__device__ __align__(16) float g_T1[BB * HH];
__device__ __align__(16) float g_T2[BB * HH];
__device__ float g_tau[BB];

// ---------------------------------------------------------------------------
// Kernel 1: per-row precompute
//   T1[i,h] = (x_i @ Wi)[h] + (x_i @ Wd)[h] + b1[h]
//   T2[i,h] = (x_i @ Wj)[h] - (x_i @ Wd)[h]
//   tau[i]  = max(softplus(x_i @ Wt + bt), 0.01) + 1
// ---------------------------------------------------------------------------
__global__ __launch_bounds__(HH) void precompute_kernel(
    const float* __restrict__ x, const float* __restrict__ W1,
    const float* __restrict__ b1, const float* __restrict__ Wt,
    const float* __restrict__ bt) {
  __shared__ float xi[DD];
  const int i = blockIdx.x;
  const int h = threadIdx.x;  // 128 threads
  if (h < DD) xi[h] = x[i * DD + h];
  __syncthreads();

  float ai = 0.f, aj = 0.f, ad = 0.f;
#pragma unroll 8
  for (int d = 0; d < DD; ++d) {
    const float xv = xi[d];
    ai += xv * W1[d * HH + h];
    aj += xv * W1[(DD + d) * HH + h];
    ad += xv * W1[(2 * DD + d) * HH + h];
  }
  g_T1[i * HH + h] = ai + ad + b1[h];
  g_T2[i * HH + h] = aj - ad;

  if (h == 0) {
    float z = bt[0];
#pragma unroll 8
    for (int d = 0; d < DD; ++d) z += xi[d] * Wt[d];
    const float sp = (z > 20.f) ? z : log1pf(expf(z));
    g_tau[i] = fmaxf(sp, 0.01f) + 1.0f;
  }
}

// ---------------------------------------------------------------------------
// Kernel 2: fused pair-GEMM + mean + MLP head + layernorm. One CTA per row i.
// ---------------------------------------------------------------------------
__global__ __launch_bounds__(256) void main_kernel(
    const float* __restrict__ x, const float* __restrict__ W1,
    const float* __restrict__ W2, const float* __restrict__ b2,
    const float* __restrict__ Wa, const float* __restrict__ ba,
    const float* __restrict__ Wr, const float* __restrict__ br,
    const float* __restrict__ gamma, const float* __restrict__ beta,
    float* __restrict__ out) {
  __shared__ __align__(16) float w_s[DD * HH];   // Wab, 32 KB
  __shared__ __align__(16) float a_s[DD * TJ];   // |x_i - x_j| tile, 8 KB
  __shared__ float xi_s[DD];
  __shared__ float aux[8 * HH];                  // per-warp partial sums
  __shared__ float S_s[HH];
  __shared__ float hm_s[HH];
  __shared__ float red[8];

  const int i = blockIdx.x;
  const int t = threadIdx.x;   // 256
  const int tj = t >> 5;       // warp id 0..7 -> j sub-block (4 j's each)
  const int th = t & 31;       // lane -> h sub-block (4 h's each)
  const int th4 = th << 2;

  // Stage Wab = W1[3D:4D] into SMEM (coalesced)
#pragma unroll
  for (int it = 0; it < 32; ++it) {
    const int e = t + it * 256;
    w_s[e] = W1[3 * DD * HH + e];
  }
  if (t < DD) xi_s[t] = x[i * DD + t];
  __syncthreads();

  const float4 t1 = *(const float4*)(g_T1 + i * HH + th4);
  float s0 = 0.f, s1 = 0.f, s2 = 0.f, s3 = 0.f;

  for (int jt = 0; jt < BB / TJ; ++jt) {
    const int j0 = jt * TJ;
    // Fill a_s[d][j] = |x[j0+j,d] - x[i,d]|  (transposed: d-major, j contiguous)
#pragma unroll
    for (int g = 0; g < 2; ++g) {
      const int e = t + g * 256;  // 0..511
      const int j = e & 31;
      const int dg = e >> 5;      // 0..15 groups of 4 d's
      const float4 xj = *(const float4*)(x + (size_t)(j0 + j) * DD + dg * 4);
      a_s[(dg * 4 + 0) * TJ + j] = fabsf(xj.x - xi_s[dg * 4 + 0]);
      a_s[(dg * 4 + 1) * TJ + j] = fabsf(xj.y - xi_s[dg * 4 + 1]);
      a_s[(dg * 4 + 2) * TJ + j] = fabsf(xj.z - xi_s[dg * 4 + 2]);
      a_s[(dg * 4 + 3) * TJ + j] = fabsf(xj.w - xi_s[dg * 4 + 3]);
    }
    __syncthreads();

    // 4x4 register-tile GEMM: c[jj][k] = sum_d a[d][tj*4+jj] * Wab[d][th4+k]
    float c00 = 0.f, c01 = 0.f, c02 = 0.f, c03 = 0.f;
    float c10 = 0.f, c11 = 0.f, c12 = 0.f, c13 = 0.f;
    float c20 = 0.f, c21 = 0.f, c22 = 0.f, c23 = 0.f;
    float c30 = 0.f, c31 = 0.f, c32 = 0.f, c33 = 0.f;
#pragma unroll 8
    for (int d = 0; d < DD; ++d) {
      const float4 w = *(const float4*)(w_s + d * HH + th4);       // coalesced
      const float4 a = *(const float4*)(a_s + d * TJ + (tj << 2)); // broadcast
      c00 += a.x * w.x; c01 += a.x * w.y; c02 += a.x * w.z; c03 += a.x * w.w;
      c10 += a.y * w.x; c11 += a.y * w.y; c12 += a.y * w.z; c13 += a.y * w.w;
      c20 += a.z * w.x; c21 += a.z * w.y; c22 += a.z * w.z; c23 += a.z * w.w;
      c30 += a.w * w.x; c31 += a.w * w.y; c32 += a.w * w.z; c33 += a.w * w.w;
    }
    // Fuse: pre = ta + T1[i] + T2[j]; relu; accumulate sum over j
    {
      const int jb = j0 + (tj << 2);
      float4 t2;
      t2 = *(const float4*)(g_T2 + (size_t)(jb + 0) * HH + th4);
      s0 += fmaxf(c00 + t1.x + t2.x, 0.f); s1 += fmaxf(c01 + t1.y + t2.y, 0.f);
      s2 += fmaxf(c02 + t1.z + t2.z, 0.f); s3 += fmaxf(c03 + t1.w + t2.w, 0.f);
      t2 = *(const float4*)(g_T2 + (size_t)(jb + 1) * HH + th4);
      s0 += fmaxf(c10 + t1.x + t2.x, 0.f); s1 += fmaxf(c11 + t1.y + t2.y, 0.f);
      s2 += fmaxf(c12 + t1.z + t2.z, 0.f); s3 += fmaxf(c13 + t1.w + t2.w, 0.f);
      t2 = *(const float4*)(g_T2 + (size_t)(jb + 2) * HH + th4);
      s0 += fmaxf(c20 + t1.x + t2.x, 0.f); s1 += fmaxf(c21 + t1.y + t2.y, 0.f);
      s2 += fmaxf(c22 + t1.z + t2.z, 0.f); s3 += fmaxf(c23 + t1.w + t2.w, 0.f);
      t2 = *(const float4*)(g_T2 + (size_t)(jb + 3) * HH + th4);
      s0 += fmaxf(c30 + t1.x + t2.x, 0.f); s1 += fmaxf(c31 + t1.y + t2.y, 0.f);
      s2 += fmaxf(c32 + t1.z + t2.z, 0.f); s3 += fmaxf(c33 + t1.w + t2.w, 0.f);
    }
    __syncthreads();  // protect a_s for next tile
  }

  // Reduce S over the 8 warp groups
  aux[tj * HH + th4 + 0] = s0;
  aux[tj * HH + th4 + 1] = s1;
  aux[tj * HH + th4 + 2] = s2;
  aux[tj * HH + th4 + 3] = s3;
  __syncthreads();
  if (t < HH) {
    float S = 0.f;
#pragma unroll
    for (int p = 0; p < 8; ++p) S += aux[p * HH + t];
    S_s[t] = S * (1.0f / BB);  // mean over j of relu(pre)
  }
  __syncthreads();

  // h_mean = (S @ W2 + b2) / tau[i]
  if (t < HH) {
    float acc = b2[t];
#pragma unroll 8
    for (int k = 0; k < HH; ++k) acc += S_s[k] * W2[k * HH + t];
    hm_s[t] = acc / g_tau[i];
  }
  __syncthreads();

  // h = relu(h_mean @ Wa + ba);  y = h + x_i @ Wr + br
  float yv = 0.f;
  if (t < HH) {
    float acc = ba[t];
#pragma unroll 8
    for (int k = 0; k < HH; ++k) acc += hm_s[k] * Wa[k * HH + t];
    const float hv = fmaxf(acc, 0.f);
    float acc2 = br[t];
#pragma unroll 8
    for (int d = 0; d < DD; ++d) acc2 += xi_s[d] * Wr[d * HH + t];
    yv = hv + acc2;
  }

  // LayerNorm over H (threads 0..127 hold y; warps 4..7 contribute zeros, ignored)
  float v = yv;
#pragma unroll
  for (int off = 16; off > 0; off >>= 1) v += __shfl_xor_sync(0xffffffffu, v, off);
  if (th == 0) red[tj] = v;
  __syncthreads();
  const float mu = (red[0] + red[1] + red[2] + red[3]) * (1.0f / HH);
  __syncthreads();  // everyone has read red before rewrite
  const float dv = (t < HH) ? (yv - mu) : 0.f;
  float v2 = dv * dv;
#pragma unroll
  for (int off = 16; off > 0; off >>= 1) v2 += __shfl_xor_sync(0xffffffffu, v2, off);
  if (th == 0) red[tj] = v2;
  __syncthreads();
  const float var = (red[0] + red[1] + red[2] + red[3]) * (1.0f / HH);

  if (t < HH) {
    out[i * HH + t] = (yv - mu) * rsqrtf(var + 1e-5f) * gamma[t] + beta[t];
  }
}

// ---------------------------------------------------------------------------
// Inputs (metadata order):
// 0:x 1:W1 2:b1 3:W2 4:b2 5:Wt 6:bt 7:Wa 8:ba 9:Wr 10:br 11:gamma 12:beta
// ---------------------------------------------------------------------------
extern "C" void kernel_launch(void* const* d_in, const int* in_sizes, int n_in,
                              void* d_out, int out_size) {
  const float* x     = (const float*)d_in[0];
  const float* W1    = (const float*)d_in[1];
  const float* b1    = (const float*)d_in[2];
  const float* W2    = (const float*)d_in[3];
  const float* b2    = (const float*)d_in[4];
  const float* Wt    = (const float*)d_in[5];
  const float* bt    = (const float*)d_in[6];
  const float* Wa    = (const float*)d_in[7];
  const float* ba    = (const float*)d_in[8];
  const float* Wr    = (const float*)d_in[9];
  const float* br    = (const float*)d_in[10];
  const float* gamma = (const float*)d_in[11];
  const float* beta  = (const float*)d_in[12];
  float* out = (float*)d_out;

  precompute_kernel<<<BB, HH>>>(x, W1, b1, Wt, bt);
  main_kernel<<<BB, 256>>>(x, W1, W2, b2, Wa, ba, Wr, br, gamma, beta, out);
}

// round 2
// speedup vs baseline: 1.5933x; 1.5933x over previous
#include <cuda_runtime.h>
#include <math.h>
#include <stdint.h>

#define BB 1024
#define DD 64
#define HH 128
#define KK 72          // 64 |delta| cols + ones cols (2 used, rest zero-pad)
#define NKS 9          // KK / 8 k-steps
#define JT 32          // j-tile
#define IB 2           // i's per CTA
#define ASTR 76        // A smem row stride (words) -> conflict-free frag loads
#define T2STR 132      // T2 smem row stride (words)

// Scratch (allocation-free rule: __device__ globals)
__device__ __align__(16) float g_T1[BB * HH];
__device__ __align__(16) float g_T2[BB * HH];
__device__ float g_tau[BB];

__device__ __forceinline__ uint32_t f2tf(float f) {
  uint32_t u;
  asm("cvt.rna.tf32.f32 %0, %1;" : "=r"(u) : "f"(f));
  return u;
}

__device__ __forceinline__ void mma8(float* c, uint32_t a0, uint32_t a1,
                                     uint32_t a2, uint32_t a3, uint32_t b0,
                                     uint32_t b1) {
  asm volatile(
      "mma.sync.aligned.m16n8k8.row.col.f32.tf32.tf32.f32 "
      "{%0,%1,%2,%3},{%4,%5,%6,%7},{%8,%9},{%0,%1,%2,%3};"
      : "+f"(c[0]), "+f"(c[1]), "+f"(c[2]), "+f"(c[3])
      : "r"(a0), "r"(a1), "r"(a2), "r"(a3), "r"(b0), "r"(b1));
}

// ---------------------------------------------------------------------------
// Kernel 1: per-row precompute
//   T1[i,h] = x_i@(Wi+Wd) + b1   T2[j,h] = x_j@(Wj-Wd)   tau[i]
// ---------------------------------------------------------------------------
__global__ __launch_bounds__(HH) void precompute_kernel(
    const float* __restrict__ x, const float* __restrict__ W1,
    const float* __restrict__ b1, const float* __restrict__ Wt,
    const float* __restrict__ bt) {
  __shared__ float xi[DD];
  const int i = blockIdx.x;
  const int h = threadIdx.x;
  if (h < DD) xi[h] = x[i * DD + h];
  __syncthreads();

  float ai = 0.f, aj = 0.f, ad = 0.f;
#pragma unroll 8
  for (int d = 0; d < DD; ++d) {
    const float xv = xi[d];
    ai += xv * W1[d * HH + h];
    aj += xv * W1[(DD + d) * HH + h];
    ad += xv * W1[(2 * DD + d) * HH + h];
  }
  g_T1[i * HH + h] = ai + ad + b1[h];
  g_T2[i * HH + h] = aj - ad;

  if (h == 0) {
    float z = bt[0];
#pragma unroll 8
    for (int d = 0; d < DD; ++d) z += xi[d] * Wt[d];
    const float sp = (z > 20.f) ? z : log1pf(expf(z));
    g_tau[i] = fmaxf(sp, 0.01f) + 1.0f;
  }
}

// ---------------------------------------------------------------------------
// Kernel 2: tf32 mma.sync pair-GEMM + fused relu-mean + head + layernorm.
// One CTA per IB=2 consecutive i's. 256 threads = 8 warps (wr in {0,1} = m16
// half of the 32-j tile, wc in {0..3} = 32-h quarter).
// ---------------------------------------------------------------------------
__global__ __launch_bounds__(256) void main_kernel(
    const float* __restrict__ x, const float* __restrict__ W1,
    const float* __restrict__ W2, const float* __restrict__ b2,
    const float* __restrict__ Wa, const float* __restrict__ ba,
    const float* __restrict__ Wr, const float* __restrict__ br,
    const float* __restrict__ gamma, const float* __restrict__ beta,
    float* __restrict__ out) {
  __shared__ __align__(16) float xs[IB][DD];
  __shared__ __align__(16) float xjs[JT * DD];
  __shared__ __align__(16) uint32_t As[JT * ASTR];
  __shared__ __align__(16) float t2s[JT * T2STR];
  __shared__ float Spart[2][IB][HH];
  __shared__ float S_s[HH];
  __shared__ float hm_s[HH];
  __shared__ float red[8];

  const int t = threadIdx.x;
  const int w = t >> 5, lane = t & 31;
  const int wr = w >> 2, wc = w & 3;
  const int g = lane >> 2, tig = lane & 3;
  const int i0 = blockIdx.x * IB;

  if (t < IB * DD) ((float*)xs)[t] = x[(size_t)i0 * DD + t];

  // B fragments (constant per CTA) -> registers. src row k: [Wab | T1[i0] |
  // T1[i0+1] | 0-pad], col n. Frag layout: b0=(k0+tig, n0+g), b1=(k0+tig+4,·).
  uint32_t Bv[NKS][4][2];
#pragma unroll
  for (int ks = 0; ks < NKS; ks++)
#pragma unroll
    for (int nt = 0; nt < 4; nt++) {
      const int n = wc * 32 + nt * 8 + g;
#pragma unroll
      for (int hf = 0; hf < 2; hf++) {
        const int k = ks * 8 + tig + hf * 4;
        float bv;
        if (k < DD) bv = W1[(size_t)(3 * DD + k) * HH + n];
        else if (k == DD) bv = g_T1[(size_t)i0 * HH + n];
        else if (k == DD + 1) bv = g_T1[(size_t)(i0 + 1) * HH + n];
        else bv = 0.f;
        Bv[ks][nt][hf] = f2tf(bv);
      }
    }

  float sacc[IB][8];
#pragma unroll
  for (int a = 0; a < IB; a++)
#pragma unroll
    for (int q = 0; q < 8; q++) sacc[a][q] = 0.f;

  const int ar = wr * 16 + g;  // local j row for c0/c1 (c2/c3: +8)

  for (int j0 = 0; j0 < BB; j0 += JT) {
    // stage x_j tile (32x64) and T2 tile (32x128)
#pragma unroll
    for (int r = 0; r < 2; r++) {
      const int e = t + r * 256;
      const int j = e >> 4, q = (e & 15) << 2;
      *(float4*)&xjs[j * DD + q] = *(const float4*)&x[(size_t)(j0 + j) * DD + q];
    }
#pragma unroll
    for (int r = 0; r < 4; r++) {
      const int e = t + r * 256;
      const int j = e >> 5, q = (e & 31) << 2;
      *(float4*)&t2s[j * T2STR + q] =
          *(const float4*)&g_T2[(size_t)(j0 + j) * HH + q];
    }
    __syncthreads();

#pragma unroll
    for (int ii = 0; ii < IB; ii++) {
      // Build A tile: [ |x_i - x_j| (64) | onehot(ii) (8) ], tf32-rounded
#pragma unroll
      for (int r = 0; r < 2; r++) {
        const int e = t + r * 256;               // 512 float4 groups
        const int row = e >> 4, cg = (e & 15) << 2;
        const float4 xj4 = *(const float4*)&xjs[row * DD + cg];
        const float4 xi4 = *(const float4*)&xs[ii][cg];
        uint4 o;
        o.x = f2tf(fabsf(xj4.x - xi4.x));
        o.y = f2tf(fabsf(xj4.y - xi4.y));
        o.z = f2tf(fabsf(xj4.z - xi4.z));
        o.w = f2tf(fabsf(xj4.w - xi4.w));
        *(uint4*)&As[row * ASTR + cg] = o;
      }
      {
        const int row = t >> 3, c = DD + (t & 7);
        As[row * ASTR + c] = (c == DD + ii) ? 0x3f800000u : 0u;
      }
      __syncthreads();

      float cc[4][4];
#pragma unroll
      for (int nt = 0; nt < 4; nt++)
#pragma unroll
        for (int q = 0; q < 4; q++) cc[nt][q] = 0.f;

#pragma unroll
      for (int ks = 0; ks < NKS; ks++) {
        const uint32_t a0 = As[ar * ASTR + ks * 8 + tig];
        const uint32_t a1 = As[(ar + 8) * ASTR + ks * 8 + tig];
        const uint32_t a2 = As[ar * ASTR + ks * 8 + tig + 4];
        const uint32_t a3 = As[(ar + 8) * ASTR + ks * 8 + tig + 4];
#pragma unroll
        for (int nt = 0; nt < 4; nt++)
          mma8(cc[nt], a0, a1, a2, a3, Bv[ks][nt][0], Bv[ks][nt][1]);
      }

      // epilogue: + T2 (fp32), relu, accumulate over j
#pragma unroll
      for (int nt = 0; nt < 4; nt++) {
        const int h0 = wc * 32 + nt * 8 + 2 * tig;
        const float2 ta = *(const float2*)&t2s[ar * T2STR + h0];
        const float2 tb = *(const float2*)&t2s[(ar + 8) * T2STR + h0];
        sacc[ii][nt * 2 + 0] +=
            fmaxf(cc[nt][0] + ta.x, 0.f) + fmaxf(cc[nt][2] + tb.x, 0.f);
        sacc[ii][nt * 2 + 1] +=
            fmaxf(cc[nt][1] + ta.y, 0.f) + fmaxf(cc[nt][3] + tb.y, 0.f);
      }
      __syncthreads();  // As/xjs/t2s reuse
    }
  }

  // Reduce sacc over the 8 row-groups g (lanes tig, tig+4, ..., tig+28)
#pragma unroll
  for (int a = 0; a < IB; a++)
#pragma unroll
    for (int q = 0; q < 8; q++) {
      float v = sacc[a][q];
      v += __shfl_xor_sync(0xffffffffu, v, 4);
      v += __shfl_xor_sync(0xffffffffu, v, 8);
      v += __shfl_xor_sync(0xffffffffu, v, 16);
      sacc[a][q] = v;
    }
  if (lane < 4) {  // g==0, tig==lane
#pragma unroll
    for (int a = 0; a < IB; a++)
#pragma unroll
      for (int nt = 0; nt < 4; nt++) {
        Spart[wr][a][wc * 32 + nt * 8 + 2 * lane + 0] = sacc[a][nt * 2 + 0];
        Spart[wr][a][wc * 32 + nt * 8 + 2 * lane + 1] = sacc[a][nt * 2 + 1];
      }
  }
  __syncthreads();

  // Head + layernorm per i
#pragma unroll
  for (int ii = 0; ii < IB; ii++) {
    if (t < HH) S_s[t] = (Spart[0][ii][t] + Spart[1][ii][t]) * (1.0f / BB);
    __syncthreads();
    if (t < HH) {
      float acc = b2[t];
#pragma unroll 8
      for (int k = 0; k < HH; ++k) acc += S_s[k] * W2[k * HH + t];
      hm_s[t] = acc / g_tau[i0 + ii];
    }
    __syncthreads();
    float yv = 0.f;
    if (t < HH) {
      float acc = ba[t];
#pragma unroll 8
      for (int k = 0; k < HH; ++k) acc += hm_s[k] * Wa[k * HH + t];
      const float hv = fmaxf(acc, 0.f);
      float a2v = br[t];
#pragma unroll 8
      for (int d = 0; d < DD; ++d) a2v += xs[ii][d] * Wr[d * HH + t];
      yv = hv + a2v;
    }
    float v = yv;
#pragma unroll
    for (int off = 16; off > 0; off >>= 1)
      v += __shfl_xor_sync(0xffffffffu, v, off);
    if (lane == 0) red[w] = v;
    __syncthreads();
    const float mu = (red[0] + red[1] + red[2] + red[3]) * (1.0f / HH);
    __syncthreads();
    const float dv = (t < HH) ? (yv - mu) : 0.f;
    float v2 = dv * dv;
#pragma unroll
    for (int off = 16; off > 0; off >>= 1)
      v2 += __shfl_xor_sync(0xffffffffu, v2, off);
    if (lane == 0) red[w] = v2;
    __syncthreads();
    const float var = (red[0] + red[1] + red[2] + red[3]) * (1.0f / HH);
    if (t < HH)
      out[(size_t)(i0 + ii) * HH + t] =
          (yv - mu) * rsqrtf(var + 1e-5f) * gamma[t] + beta[t];
    __syncthreads();
  }
}

// ---------------------------------------------------------------------------
// Inputs: 0:x 1:W1 2:b1 3:W2 4:b2 5:Wt 6:bt 7:Wa 8:ba 9:Wr 10:br 11:gamma 12:beta
// ---------------------------------------------------------------------------
extern "C" void kernel_launch(void* const* d_in, const int* in_sizes, int n_in,
                              void* d_out, int out_size) {
  const float* x     = (const float*)d_in[0];
  const float* W1    = (const float*)d_in[1];
  const float* b1    = (const float*)d_in[2];
  const float* W2    = (const float*)d_in[3];
  const float* b2    = (const float*)d_in[4];
  const float* Wt    = (const float*)d_in[5];
  const float* bt    = (const float*)d_in[6];
  const float* Wa    = (const float*)d_in[7];
  const float* ba    = (const float*)d_in[8];
  const float* Wr    = (const float*)d_in[9];
  const float* br    = (const float*)d_in[10];
  const float* gamma = (const float*)d_in[11];
  const float* beta  = (const float*)d_in[12];
  float* out = (float*)d_out;

  precompute_kernel<<<BB, HH>>>(x, W1, b1, Wt, bt);
  main_kernel<<<BB / IB, 256>>>(x, W1, W2, b2, Wa, ba, Wr, br, gamma, beta,
                                out);
}

// round 3
// speedup vs baseline: 3.1387x; 1.9700x over previous
#include <cuda_runtime.h>
#include <cuda_bf16.h>
#include <math.h>
#include <stdint.h>

#define BB 1024
#define DD 64
#define HH 128
#define NKS 4          // K=64 -> 4 k-steps of 16 (bf16 mma)
#define JT 32          // j-tile
#define IB 2           // i's per CTA
#define ASTR 36        // A smem row stride in u32 words (32 + pad)
#define T2STR 132      // T2 smem row stride (words)

// Scratch (allocation-free rule: __device__ globals)
__device__ __align__(16) float g_T1[BB * HH];
__device__ __align__(16) float g_T2[BB * HH];
__device__ float g_tau[BB];

__device__ __forceinline__ uint32_t pack_bf2(float lo, float hi) {
  __nv_bfloat162 v = __floats2bfloat162_rn(lo, hi);
  return *(uint32_t*)&v;
}

__device__ __forceinline__ void mma16(float* c, uint32_t a0, uint32_t a1,
                                      uint32_t a2, uint32_t a3, uint32_t b0,
                                      uint32_t b1) {
  asm volatile(
      "mma.sync.aligned.m16n8k16.row.col.f32.bf16.bf16.f32 "
      "{%0,%1,%2,%3},{%4,%5,%6,%7},{%8,%9},{%0,%1,%2,%3};"
      : "+f"(c[0]), "+f"(c[1]), "+f"(c[2]), "+f"(c[3])
      : "r"(a0), "r"(a1), "r"(a2), "r"(a3), "r"(b0), "r"(b1));
}

// ---------------------------------------------------------------------------
// Kernel 1: per-row precompute
//   T1[i,h] = x_i@(Wi+Wd) + b1   T2[j,h] = x_j@(Wj-Wd)   tau[i]
// ---------------------------------------------------------------------------
__global__ __launch_bounds__(HH) void precompute_kernel(
    const float* __restrict__ x, const float* __restrict__ W1,
    const float* __restrict__ b1, const float* __restrict__ Wt,
    const float* __restrict__ bt) {
  __shared__ float xi[DD];
  const int i = blockIdx.x;
  const int h = threadIdx.x;
  if (h < DD) xi[h] = x[i * DD + h];
  __syncthreads();

  float ai = 0.f, aj = 0.f, ad = 0.f;
#pragma unroll 8
  for (int d = 0; d < DD; ++d) {
    const float xv = xi[d];
    ai += xv * W1[d * HH + h];
    aj += xv * W1[(DD + d) * HH + h];
    ad += xv * W1[(2 * DD + d) * HH + h];
  }
  g_T1[i * HH + h] = ai + ad + b1[h];
  g_T2[i * HH + h] = aj - ad;

  if (h == 0) {
    float z = bt[0];
#pragma unroll 8
    for (int d = 0; d < DD; ++d) z += xi[d] * Wt[d];
    const float sp = (z > 20.f) ? z : log1pf(expf(z));
    g_tau[i] = fmaxf(sp, 0.01f) + 1.0f;
  }
}

// ---------------------------------------------------------------------------
// Kernel 2: bf16 m16n8k16 pair-GEMM + fused relu-mean + head + layernorm.
// One CTA per IB=2 i's. 8 warps: wr in {0,1} = 16-row half of j-tile,
// wc in {0..3} = 32-h quarter. T1/T2 added fp32 in epilogue.
// ---------------------------------------------------------------------------
__global__ __launch_bounds__(256, 2) void main_kernel(
    const float* __restrict__ x, const float* __restrict__ W1,
    const float* __restrict__ W2, const float* __restrict__ b2,
    const float* __restrict__ Wa, const float* __restrict__ ba,
    const float* __restrict__ Wr, const float* __restrict__ br,
    const float* __restrict__ gamma, const float* __restrict__ beta,
    float* __restrict__ out) {
  __shared__ __align__(16) float xs[IB][DD];
  __shared__ __align__(16) float xjs[JT * DD];
  __shared__ __align__(16) uint32_t As[IB][JT * ASTR];  // bf16x2 packed
  __shared__ __align__(16) float t2s[JT * T2STR];
  __shared__ float Spart[2][IB][HH];
  __shared__ float S_s[HH];
  __shared__ float hm_s[HH];
  __shared__ float red[8];

  const int t = threadIdx.x;
  const int w = t >> 5, lane = t & 31;
  const int wr = w >> 2, wc = w & 3;
  const int g = lane >> 2, tig = lane & 3;
  const int i0 = blockIdx.x * IB;

  if (t < IB * DD) ((float*)xs)[t] = x[(size_t)i0 * DD + t];

  // B fragments (Wab, constant per CTA) -> bf16x2 registers.
  // b0 = pack(B[ks*16+2tig][n], B[ks*16+2tig+1][n]); b1 = same +8 k.
  uint32_t Bv[NKS][4][2];
#pragma unroll
  for (int ks = 0; ks < NKS; ks++)
#pragma unroll
    for (int nt = 0; nt < 4; nt++) {
      const int n = wc * 32 + nt * 8 + g;
#pragma unroll
      for (int hf = 0; hf < 2; hf++) {
        const int k = ks * 16 + 2 * tig + hf * 8;
        Bv[ks][nt][hf] = pack_bf2(W1[(size_t)(3 * DD + k) * HH + n],
                                  W1[(size_t)(3 * DD + k + 1) * HH + n]);
      }
    }

  // T1 per-thread columns (fp32, added in epilogue)
  float2 t1v[IB][4];
#pragma unroll
  for (int ii = 0; ii < IB; ii++)
#pragma unroll
    for (int nt = 0; nt < 4; nt++)
      t1v[ii][nt] = *(const float2*)&g_T1[(size_t)(i0 + ii) * HH + wc * 32 +
                                          nt * 8 + 2 * tig];

  float sacc[IB][8];
#pragma unroll
  for (int a = 0; a < IB; a++)
#pragma unroll
    for (int q = 0; q < 8; q++) sacc[a][q] = 0.f;

  const int ar = wr * 16 + g;  // local j row for c0/c1 (c2/c3: +8)

  for (int j0 = 0; j0 < BB; j0 += JT) {
    __syncthreads();  // previous tile's reads of xjs/t2s/As done
    // stage x_j tile (32x64) and T2 tile (32x128)
#pragma unroll
    for (int r = 0; r < 2; r++) {
      const int e = t + r * 256;
      const int j = e >> 4, q = (e & 15) << 2;
      *(float4*)&xjs[j * DD + q] = *(const float4*)&x[(size_t)(j0 + j) * DD + q];
    }
#pragma unroll
    for (int r = 0; r < 4; r++) {
      const int e = t + r * 256;
      const int j = e >> 5, q = (e & 31) << 2;
      *(float4*)&t2s[j * T2STR + q] =
          *(const float4*)&g_T2[(size_t)(j0 + j) * HH + q];
    }
    __syncthreads();

    // Build BOTH A tiles (bf16 |x_i - x_j|), then run MMAs uninterrupted
#pragma unroll
    for (int ii = 0; ii < IB; ii++) {
#pragma unroll
      for (int r = 0; r < 2; r++) {
        const int e = t + r * 256;          // 512 groups of 4 k's
        const int row = e >> 4, cg = e & 15;  // cg: group of 2 u32 = 4 floats
        const float4 xj4 = *(const float4*)&xjs[row * DD + cg * 4];
        const float4 xi4 = *(const float4*)&xs[ii][cg * 4];
        uint2 o;
        o.x = pack_bf2(fabsf(xj4.x - xi4.x), fabsf(xj4.y - xi4.y));
        o.y = pack_bf2(fabsf(xj4.z - xi4.z), fabsf(xj4.w - xi4.w));
        *(uint2*)&As[ii][row * ASTR + cg * 2] = o;
      }
    }
    __syncthreads();

#pragma unroll
    for (int ii = 0; ii < IB; ii++) {
      float cc[4][4];
#pragma unroll
      for (int nt = 0; nt < 4; nt++)
#pragma unroll
        for (int q = 0; q < 4; q++) cc[nt][q] = 0.f;

#pragma unroll
      for (int ks = 0; ks < NKS; ks++) {
        const uint32_t a0 = As[ii][ar * ASTR + ks * 8 + tig];
        const uint32_t a1 = As[ii][(ar + 8) * ASTR + ks * 8 + tig];
        const uint32_t a2 = As[ii][ar * ASTR + ks * 8 + tig + 4];
        const uint32_t a3 = As[ii][(ar + 8) * ASTR + ks * 8 + tig + 4];
#pragma unroll
        for (int nt = 0; nt < 4; nt++)
          mma16(cc[nt], a0, a1, a2, a3, Bv[ks][nt][0], Bv[ks][nt][1]);
      }

      // epilogue: + T1[i] + T2[j] (fp32), relu, accumulate over j
#pragma unroll
      for (int nt = 0; nt < 4; nt++) {
        const int h0 = wc * 32 + nt * 8 + 2 * tig;
        const float2 ta = *(const float2*)&t2s[ar * T2STR + h0];
        const float2 tb = *(const float2*)&t2s[(ar + 8) * T2STR + h0];
        const float2 t1 = t1v[ii][nt];
        sacc[ii][nt * 2 + 0] += fmaxf(cc[nt][0] + t1.x + ta.x, 0.f) +
                                fmaxf(cc[nt][2] + t1.x + tb.x, 0.f);
        sacc[ii][nt * 2 + 1] += fmaxf(cc[nt][1] + t1.y + ta.y, 0.f) +
                                fmaxf(cc[nt][3] + t1.y + tb.y, 0.f);
      }
    }
  }

  // Reduce sacc over the 8 row-groups g (shfl within warp)
#pragma unroll
  for (int a = 0; a < IB; a++)
#pragma unroll
    for (int q = 0; q < 8; q++) {
      float v = sacc[a][q];
      v += __shfl_xor_sync(0xffffffffu, v, 4);
      v += __shfl_xor_sync(0xffffffffu, v, 8);
      v += __shfl_xor_sync(0xffffffffu, v, 16);
      sacc[a][q] = v;
    }
  __syncthreads();  // As reads done before Spart aliasing concerns (distinct)
  if (lane < 4) {  // g==0, tig==lane
#pragma unroll
    for (int a = 0; a < IB; a++)
#pragma unroll
      for (int nt = 0; nt < 4; nt++) {
        Spart[wr][a][wc * 32 + nt * 8 + 2 * lane + 0] = sacc[a][nt * 2 + 0];
        Spart[wr][a][wc * 32 + nt * 8 + 2 * lane + 1] = sacc[a][nt * 2 + 1];
      }
  }
  __syncthreads();

  // Head + layernorm per i
#pragma unroll
  for (int ii = 0; ii < IB; ii++) {
    if (t < HH) S_s[t] = (Spart[0][ii][t] + Spart[1][ii][t]) * (1.0f / BB);
    __syncthreads();
    if (t < HH) {
      float acc = b2[t];
#pragma unroll 8
      for (int k = 0; k < HH; ++k) acc += S_s[k] * W2[k * HH + t];
      hm_s[t] = acc / g_tau[i0 + ii];
    }
    __syncthreads();
    float yv = 0.f;
    if (t < HH) {
      float acc = ba[t];
#pragma unroll 8
      for (int k = 0; k < HH; ++k) acc += hm_s[k] * Wa[k * HH + t];
      const float hv = fmaxf(acc, 0.f);
      float a2v = br[t];
#pragma unroll 8
      for (int d = 0; d < DD; ++d) a2v += xs[ii][d] * Wr[d * HH + t];
      yv = hv + a2v;
    }
    float v = yv;
#pragma unroll
    for (int off = 16; off > 0; off >>= 1)
      v += __shfl_xor_sync(0xffffffffu, v, off);
    if (lane == 0) red[w] = v;
    __syncthreads();
    const float mu = (red[0] + red[1] + red[2] + red[3]) * (1.0f / HH);
    __syncthreads();
    const float dv = (t < HH) ? (yv - mu) : 0.f;
    float v2 = dv * dv;
#pragma unroll
    for (int off = 16; off > 0; off >>= 1)
      v2 += __shfl_xor_sync(0xffffffffu, v2, off);
    if (lane == 0) red[w] = v2;
    __syncthreads();
    const float var = (red[0] + red[1] + red[2] + red[3]) * (1.0f / HH);
    if (t < HH)
      out[(size_t)(i0 + ii) * HH + t] =
          (yv - mu) * rsqrtf(var + 1e-5f) * gamma[t] + beta[t];
    __syncthreads();
  }
}

// ---------------------------------------------------------------------------
// Inputs: 0:x 1:W1 2:b1 3:W2 4:b2 5:Wt 6:bt 7:Wa 8:ba 9:Wr 10:br 11:gamma 12:beta
// ---------------------------------------------------------------------------
extern "C" void kernel_launch(void* const* d_in, const int* in_sizes, int n_in,
                              void* d_out, int out_size) {
  const float* x     = (const float*)d_in[0];
  const float* W1    = (const float*)d_in[1];
  const float* b1    = (const float*)d_in[2];
  const float* W2    = (const float*)d_in[3];
  const float* b2    = (const float*)d_in[4];
  const float* Wt    = (const float*)d_in[5];
  const float* bt    = (const float*)d_in[6];
  const float* Wa    = (const float*)d_in[7];
  const float* ba    = (const float*)d_in[8];
  const float* Wr    = (const float*)d_in[9];
  const float* br    = (const float*)d_in[10];
  const float* gamma = (const float*)d_in[11];
  const float* beta  = (const float*)d_in[12];
  float* out = (float*)d_out;

  precompute_kernel<<<BB, HH>>>(x, W1, b1, Wt, bt);
  main_kernel<<<BB / IB, 256>>>(x, W1, W2, b2, Wa, ba, Wr, br, gamma, beta,
                                out);
}